// round 2
// baseline (speedup 1.0000x reference)
#include <cuda_runtime.h>
#include <cstdint>

// GCN: out[dst] += w * (data @ theta)[src]   (projection hoisted before scatter by linearity)
// Inputs (metadata order): src[E] i32, dst[E] i32, w[E] f32, data[N*64] f32,
//                          theta[64*64] f32, num_nodes i32 (scalar, unused — derive from sizes)

#define D 64
#define MAX_NODES 100000

// scratch: projected features data @ theta, [N, 64]
__device__ float g_proj[(size_t)MAX_NODES * D];

// ---------------------------------------------------------------------------
// zero the output (it is poisoned before timing)
__global__ void __launch_bounds__(256) zero_kernel(float4* out, int n4) {
    int i = blockIdx.x * blockDim.x + threadIdx.x;
    if (i < n4) out[i] = make_float4(0.f, 0.f, 0.f, 0.f);
}

// ---------------------------------------------------------------------------
// proj = data @ theta     [N,64] x [64,64] -> [N,64]
// theta cached in smem; each thread owns one output column for a strided set
// of rows. Per-warp the data load is uniform (broadcast) and the smem theta
// read is 32 consecutive floats (conflict-free).
__global__ void __launch_bounds__(256) proj_kernel(const float* __restrict__ data,
                                                   const float* __restrict__ theta,
                                                   float* __restrict__ proj,
                                                   int n_rows) {
    __shared__ float s_theta[D * D];
    for (int i = threadIdx.x; i < D * D; i += blockDim.x)
        s_theta[i] = theta[i];
    __syncthreads();

    const int col = threadIdx.x & (D - 1);       // 0..63
    const int row_in_blk = threadIdx.x >> 6;     // 0..3
    const int ROWS_PER_BLOCK = 64;
    const int row0 = blockIdx.x * ROWS_PER_BLOCK;

    for (int r = row0 + row_in_blk; r < row0 + ROWS_PER_BLOCK && r < n_rows; r += 4) {
        const float* __restrict__ drow = data + (size_t)r * D;
        float acc = 0.f;
        #pragma unroll
        for (int k = 0; k < D; k += 4) {
            // vectorized uniform load of 4 data elements (same for all 64 col-threads)
            float4 dv = *reinterpret_cast<const float4*>(drow + k);
            acc += dv.x * s_theta[(k + 0) * D + col];
            acc += dv.y * s_theta[(k + 1) * D + col];
            acc += dv.z * s_theta[(k + 2) * D + col];
            acc += dv.w * s_theta[(k + 3) * D + col];
        }
        proj[(size_t)r * D + col] = acc;
    }
}

// ---------------------------------------------------------------------------
// scatter: out[dst[e]] += w[e] * proj[src[e]]
// 16 threads per edge, each handling one float4 (4 of the 64 channels).
__global__ void __launch_bounds__(256) scatter_kernel(const int* __restrict__ src,
                                                      const int* __restrict__ dst,
                                                      const float* __restrict__ w,
                                                      const float4* __restrict__ proj4,
                                                      float* __restrict__ out,
                                                      int n_edges) {
    int gt = blockIdx.x * blockDim.x + threadIdx.x;
    int e = gt >> 4;
    int lane = gt & 15;
    if (e >= n_edges) return;

    int s = src[e];
    int d = dst[e];
    float wv = w[e];

    float4 v = proj4[(size_t)s * (D / 4) + lane];
    float* o = out + (size_t)d * D + lane * 4;
    atomicAdd(o + 0, wv * v.x);
    atomicAdd(o + 1, wv * v.y);
    atomicAdd(o + 2, wv * v.z);
    atomicAdd(o + 3, wv * v.w);
}

// ---------------------------------------------------------------------------
extern "C" void kernel_launch(void* const* d_in, const int* in_sizes, int n_in,
                              void* d_out, int out_size) {
    const int*   src   = (const int*)  d_in[0];
    const int*   dst   = (const int*)  d_in[1];
    const float* w     = (const float*)d_in[2];
    const float* data  = (const float*)d_in[3];
    const float* theta = (const float*)d_in[4];
    // d_in[5] = num_nodes scalar on device; derive host-side from sizes instead.

    const int n_edges = in_sizes[0];
    const int n_nodes = in_sizes[3] / D;

    float* out = (float*)d_out;
    float* proj;
    cudaGetSymbolAddress((void**)&proj, g_proj);

    // 1) zero output
    {
        int n4 = out_size / 4;
        int blocks = (n4 + 255) / 256;
        zero_kernel<<<blocks, 256>>>((float4*)out, n4);
    }
    // 2) proj = data @ theta
    {
        int blocks = (n_nodes + 63) / 64;
        proj_kernel<<<blocks, 256>>>(data, theta, proj, n_nodes);
    }
    // 3) scatter-add
    {
        long long total = (long long)n_edges * 16;
        int blocks = (int)((total + 255) / 256);
        scatter_kernel<<<blocks, 256>>>(src, dst, w, (const float4*)proj, out, n_edges);
    }
}

// round 3
// speedup vs baseline: 1.6123x; 1.6123x over previous
#include <cuda_runtime.h>
#include <cstdint>

// GCN: out[dst] += w * (data @ theta)[src]   (projection hoisted before scatter by linearity)
// Inputs (metadata order): src[E] i32, dst[E] i32, w[E] f32, data[N*64] f32,
//                          theta[64*64] f32, num_nodes (unused; derived from sizes)

#define D 64
#define MAX_NODES 100000

// scratch: projected features data @ theta, [N, 64]
__device__ float g_proj[(size_t)MAX_NODES * D];

// ---------------------------------------------------------------------------
// zero the output (it is poisoned before timing)
__global__ void __launch_bounds__(256) zero_kernel(float4* out, int n4) {
    int i = blockIdx.x * blockDim.x + threadIdx.x;
    if (i < n4) out[i] = make_float4(0.f, 0.f, 0.f, 0.f);
}

// ---------------------------------------------------------------------------
// proj = data @ theta     [N,64] x [64,64] -> [N,64]  (unchanged from R1)
__global__ void __launch_bounds__(256) proj_kernel(const float* __restrict__ data,
                                                   const float* __restrict__ theta,
                                                   float* __restrict__ proj,
                                                   int n_rows) {
    __shared__ float s_theta[D * D];
    for (int i = threadIdx.x; i < D * D; i += blockDim.x)
        s_theta[i] = theta[i];
    __syncthreads();

    const int col = threadIdx.x & (D - 1);       // 0..63
    const int row_in_blk = threadIdx.x >> 6;     // 0..3
    const int ROWS_PER_BLOCK = 64;
    const int row0 = blockIdx.x * ROWS_PER_BLOCK;

    for (int r = row0 + row_in_blk; r < row0 + ROWS_PER_BLOCK && r < n_rows; r += 4) {
        const float* __restrict__ drow = data + (size_t)r * D;
        float acc = 0.f;
        #pragma unroll
        for (int k = 0; k < D; k += 4) {
            float4 dv = *reinterpret_cast<const float4*>(drow + k);
            acc += dv.x * s_theta[(k + 0) * D + col];
            acc += dv.y * s_theta[(k + 1) * D + col];
            acc += dv.z * s_theta[(k + 2) * D + col];
            acc += dv.w * s_theta[(k + 3) * D + col];
        }
        proj[(size_t)r * D + col] = acc;
    }
}

// ---------------------------------------------------------------------------
// vectorized 16B global reduction (sm_90+): one RED op instead of four
__device__ __forceinline__ void red_add_v4(float* addr, float4 v) {
    asm volatile("red.global.add.v4.f32 [%0], {%1, %2, %3, %4};"
                 :: "l"(addr), "f"(v.x), "f"(v.y), "f"(v.z), "f"(v.w)
                 : "memory");
}

// scatter: out[dst[e]] += w[e] * proj[src[e]]
// 16 threads per edge, each handling one float4 (4 of the 64 channels) with
// a single red.v4 op.
__global__ void __launch_bounds__(256) scatter_kernel(const int* __restrict__ src,
                                                      const int* __restrict__ dst,
                                                      const float* __restrict__ w,
                                                      const float4* __restrict__ proj4,
                                                      float* __restrict__ out,
                                                      int n_edges) {
    int gt = blockIdx.x * blockDim.x + threadIdx.x;
    int e = gt >> 4;
    int lane = gt & 15;
    if (e >= n_edges) return;

    int s = src[e];
    int d = dst[e];
    float wv = w[e];

    float4 v = proj4[(size_t)s * (D / 4) + lane];
    float4 r = make_float4(wv * v.x, wv * v.y, wv * v.z, wv * v.w);
    red_add_v4(out + (size_t)d * D + lane * 4, r);
}

// ---------------------------------------------------------------------------
extern "C" void kernel_launch(void* const* d_in, const int* in_sizes, int n_in,
                              void* d_out, int out_size) {
    const int*   src   = (const int*)  d_in[0];
    const int*   dst   = (const int*)  d_in[1];
    const float* w     = (const float*)d_in[2];
    const float* data  = (const float*)d_in[3];
    const float* theta = (const float*)d_in[4];

    const int n_edges = in_sizes[0];
    const int n_nodes = in_sizes[3] / D;

    float* out = (float*)d_out;
    float* proj;
    cudaGetSymbolAddress((void**)&proj, g_proj);

    // 1) zero output
    {
        int n4 = out_size / 4;
        int blocks = (n4 + 255) / 256;
        zero_kernel<<<blocks, 256>>>((float4*)out, n4);
    }
    // 2) proj = data @ theta
    {
        int blocks = (n_nodes + 63) / 64;
        proj_kernel<<<blocks, 256>>>(data, theta, proj, n_nodes);
    }
    // 3) scatter-add (vectorized RED)
    {
        long long total = (long long)n_edges * 16;
        int blocks = (int)((total + 255) / 256);
        scatter_kernel<<<blocks, 256>>>(src, dst, w, (const float4*)proj, out, n_edges);
    }
}